// round 3
// baseline (speedup 1.0000x reference)
#include <cuda_runtime.h>
#include <math.h>

// Problem constants
#define NB   16
#define NL   511
#define NS   512
#define ND   1024
#define NHID 512
#define NDFF 2048
#define NEA  256
#define NNH  4
#define NHD  256   // head dim

// ---------------- device scratch ----------------
__device__ float g_h  [NB*NS*ND];
__device__ float g_mem[NB*NS*ND];
__device__ float g_qkv[NB*NS*3*ND];
__device__ float g_att[NB*NNH*NS*NS];
__device__ float g_ao [NB*NS*ND];
__device__ float g_ff [NB*NS*NDFF];
__device__ float g_p1 [NB*NS*NHID];

// ---------------- generic tiled GEMM -------------
// C[M,N] = act(alpha * A @ op(B) + bias) + resid
// TRANSB=true : op(B) = B^T with B as [N,K] row-major (linear layers, Q@K^T)
// TRANSB=false: op(B) = B   with B as [K,N] row-major (P@V)
// Batched over blockIdx.z with (z/nh, z%nh) offset decomposition.
// Requires M%128==0, N%128==0, K%8==0 (true for every call here).
template<bool TRANSB>
__global__ __launch_bounds__(256) void k_gemm(
    const float* __restrict__ A, int lda, long long strAb, long long strAh,
    const float* __restrict__ Bm, int ldb, long long strBb, long long strBh,
    float* __restrict__ C, int ldc, long long strCb, long long strCh,
    const float* __restrict__ bias,
    const float* __restrict__ resid,
    int M, int N, int K, int nh, float alpha, int act, int causal)
{
    int z = blockIdx.z;
    int zb = z / nh, zh = z % nh;
    A  += zb*strAb + zh*strAh;
    Bm += zb*strBb + zh*strBh;
    C  += zb*strCb + zh*strCh;

    int m0 = blockIdx.y * 128, n0 = blockIdx.x * 128;
    if (causal && n0 > m0) return;   // fully-masked tile

    __shared__ float As[8][128];
    __shared__ float Bs[8][128];

    int tid = threadIdx.x;
    int ar = tid >> 1, ak = (tid & 1) * 4;   // A/W loads: 128 rows x 8 cols
    int ty = tid >> 4, tx = tid & 15;        // 8x8 microtile coords

    float acc[8][8];
    #pragma unroll
    for (int i = 0; i < 8; i++)
        #pragma unroll
        for (int j = 0; j < 8; j++) acc[i][j] = 0.f;

    for (int k0 = 0; k0 < K; k0 += 8) {
        float4 av = *(const float4*)(A + (long long)(m0 + ar)*lda + k0 + ak);
        As[ak+0][ar] = av.x; As[ak+1][ar] = av.y;
        As[ak+2][ar] = av.z; As[ak+3][ar] = av.w;
        if (TRANSB) {
            float4 bv = *(const float4*)(Bm + (long long)(n0 + ar)*ldb + k0 + ak);
            Bs[ak+0][ar] = bv.x; Bs[ak+1][ar] = bv.y;
            Bs[ak+2][ar] = bv.z; Bs[ak+3][ar] = bv.w;
        } else {
            int bk = tid >> 5, bn = (tid & 31) * 4;
            float4 bv = *(const float4*)(Bm + (long long)(k0 + bk)*ldb + n0 + bn);
            *(float4*)&Bs[bk][bn] = bv;
        }
        __syncthreads();
        #pragma unroll
        for (int kk = 0; kk < 8; kk++) {
            float a[8], b[8];
            *(float4*)(a)   = *(const float4*)&As[kk][ty*8];
            *(float4*)(a+4) = *(const float4*)&As[kk][ty*8+4];
            *(float4*)(b)   = *(const float4*)&Bs[kk][tx*8];
            *(float4*)(b+4) = *(const float4*)&Bs[kk][tx*8+4];
            #pragma unroll
            for (int i = 0; i < 8; i++)
                #pragma unroll
                for (int j = 0; j < 8; j++)
                    acc[i][j] += a[i] * b[j];
        }
        __syncthreads();
    }

    #pragma unroll
    for (int i = 0; i < 8; i++) {
        long long row = m0 + ty*8 + i;
        #pragma unroll
        for (int j = 0; j < 8; j++) {
            int col = n0 + tx*8 + j;
            float v = acc[i][j] * alpha;
            if (bias) v += bias[col];
            if (act == 1) v = fmaxf(v, 0.f);
            else if (act == 2) v = (v >= 0.f) ? v : 0.01f * v;
            if (resid) v += resid[row*ldc + col];
            C[row*ldc + col] = v;
        }
    }
}

// ---------------- softmax over rows of S=512 ----------------
__global__ __launch_bounds__(256) void k_softmax(float* __restrict__ att, int causal)
{
    int gid = blockIdx.x;                    // b*NNH*NS + h*NS + i
    int i = gid & (NS - 1);
    float* row = att + (long long)gid * NS;
    int len = causal ? (i + 1) : NS;
    int t = threadIdx.x;

    float v0 = (t       < len) ? row[t]       : -1e30f;
    float v1 = (t + 256 < len) ? row[t + 256] : -1e30f;

    __shared__ float red[8];
    float m = fmaxf(v0, v1);
    #pragma unroll
    for (int off = 16; off; off >>= 1) m = fmaxf(m, __shfl_xor_sync(0xFFFFFFFFu, m, off));
    if ((t & 31) == 0) red[t >> 5] = m;
    __syncthreads();
    float mm = red[0];
    #pragma unroll
    for (int w = 1; w < 8; w++) mm = fmaxf(mm, red[w]);
    __syncthreads();

    float e0 = (t       < len) ? __expf(v0 - mm) : 0.f;
    float e1 = (t + 256 < len) ? __expf(v1 - mm) : 0.f;
    float s = e0 + e1;
    #pragma unroll
    for (int off = 16; off; off >>= 1) s += __shfl_xor_sync(0xFFFFFFFFu, s, off);
    if ((t & 31) == 0) red[t >> 5] = s;
    __syncthreads();
    float ss = 0.f;
    #pragma unroll
    for (int w = 0; w < 8; w++) ss += red[w];
    float inv = 1.f / ss;

    row[t]       = e0 * inv;
    row[t + 256] = e1 * inv;
}

// ---------------- LayerNorm over D=1024 (in place) ----------------
__global__ __launch_bounds__(256) void k_ln(float* __restrict__ h,
                                            const float* __restrict__ w,
                                            const float* __restrict__ b)
{
    float* x = h + (long long)blockIdx.x * ND;
    int t = threadIdx.x;
    float v[4];
    float s = 0.f;
    #pragma unroll
    for (int k = 0; k < 4; k++) { v[k] = x[t + k*256]; s += v[k]; }

    __shared__ float red[8];
    #pragma unroll
    for (int off = 16; off; off >>= 1) s += __shfl_xor_sync(0xFFFFFFFFu, s, off);
    if ((t & 31) == 0) red[t >> 5] = s;
    __syncthreads();
    float sum = 0.f;
    #pragma unroll
    for (int w2 = 0; w2 < 8; w2++) sum += red[w2];
    float mean = sum * (1.f / ND);
    __syncthreads();

    float sq = 0.f;
    #pragma unroll
    for (int k = 0; k < 4; k++) { float d = v[k] - mean; sq += d*d; }
    #pragma unroll
    for (int off = 16; off; off >>= 1) sq += __shfl_xor_sync(0xFFFFFFFFu, sq, off);
    if ((t & 31) == 0) red[t >> 5] = sq;
    __syncthreads();
    float var = 0.f;
    #pragma unroll
    for (int w2 = 0; w2 < 8; w2++) var += red[w2];
    float rstd = rsqrtf(var * (1.f / ND) + 1e-5f);

    #pragma unroll
    for (int k = 0; k < 4; k++) {
        int j = t + k*256;
        x[j] = (v[k] - mean) * rstd * w[j] + b[j];
    }
}

// ---------------- input stage: h1 = leaky(t*w1 + b1) ----------------
__global__ void k_build_h1(const float* __restrict__ target,
                           const float* __restrict__ bos,
                           const float* __restrict__ w1,
                           const float* __restrict__ b1,
                           float* __restrict__ h1)
{
    int idx = blockIdx.x * blockDim.x + threadIdx.x;   // NB*NS*NHID
    int j = idx % NHID;
    int bs = idx / NHID;
    int s = bs % NS, bb = bs / NS;
    float t = (s == 0) ? bos[0] : target[bb*NL + s - 1];
    float v = t * w1[j] + b1[j];
    h1[idx] = (v >= 0.f) ? v : 0.01f * v;
}

// ---------------- fill tgt (+PE, +prev/cur) and mem ----------------
__global__ void k_fill(const float* __restrict__ gs,
                       const float* __restrict__ prev,
                       const float* __restrict__ cur,
                       float* __restrict__ h, float* __restrict__ mem)
{
    int idx = blockIdx.x * blockDim.x + threadIdx.x;   // NB*NS*ND
    int j = idx % ND;
    int bs = idx / ND;
    int s = bs % NS, bb = bs / NS;
    float hv, mv;
    if (j < NHID) {
        int jj = j & ~1;
        float div = expf(-logf(10000.f) * (float)jj / (float)NHID);
        float ang = (float)s * div;
        float pe = (j & 1) ? cosf(ang) : sinf(ang);
        hv = h[idx] + pe;
        mv = gs[(long long)bs * NHID + j];
    } else if (j < NHID + NEA) {
        float p = prev[bb*NEA + (j - NHID)];
        hv = p; mv = p;
    } else {
        float c = cur[bb*NEA + (j - NHID - NEA)];
        hv = c; mv = c;
    }
    h[idx] = hv;
    mem[idx] = mv;
}

// ---------------- output head: dot with proj_w2, mask ----------------
__global__ void k_final(const float* __restrict__ p1,
                        const float* __restrict__ w2,
                        const float* __restrict__ b2,
                        const int* __restrict__ basis,
                        float* __restrict__ out)
{
    int warp = (blockIdx.x * blockDim.x + threadIdx.x) >> 5;
    int lane = threadIdx.x & 31;
    if (warp >= NB * NL) return;
    int bb = warp / NL, l = warp % NL;
    const float* rowp = p1 + ((long long)bb * NS + l + 1) * NHID;
    float sum = 0.f;
    #pragma unroll 4
    for (int j = lane; j < NHID; j += 32) sum += rowp[j] * w2[j];
    #pragma unroll
    for (int off = 16; off; off >>= 1) sum += __shfl_xor_sync(0xFFFFFFFFu, sum, off);
    if (lane == 0)
        out[warp] = (l < basis[bb]) ? (sum + b2[0]) : 0.f;
}

// ---------------- host side ----------------
static void gemm_tn(const float* A, int lda, const float* W, int ldb,
                    float* C, int ldc, const float* bias, const float* resid,
                    int M, int N, int K, float alpha, int act)
{
    dim3 g(N / 128, M / 128, 1);
    k_gemm<true><<<g, 256>>>(A, lda, 0, 0, W, ldb, 0, 0, C, ldc, 0, 0,
                             bias, resid, M, N, K, 1, alpha, act, 0);
}

extern "C" void kernel_launch(void* const* d_in, const int* in_sizes, int n_in,
                              void* d_out, int out_size)
{
    const float* gs      = (const float*)d_in[0];
    const float* prev    = (const float*)d_in[1];
    const float* cur     = (const float*)d_in[2];
    const float* target  = (const float*)d_in[3];
    const float* bos     = (const float*)d_in[4];
    const float* inp_w1  = (const float*)d_in[5];
    const float* inp_b1  = (const float*)d_in[6];
    const float* inp_w2  = (const float*)d_in[7];
    const float* inp_b2  = (const float*)d_in[8];
    const float* sa_qkv_w = (const float*)d_in[9];
    const float* sa_qkv_b = (const float*)d_in[10];
    const float* sa_out_w = (const float*)d_in[11];
    const float* sa_out_b = (const float*)d_in[12];
    const float* ca_qkv_w = (const float*)d_in[13];
    const float* ca_qkv_b = (const float*)d_in[14];
    const float* ca_out_w = (const float*)d_in[15];
    const float* ca_out_b = (const float*)d_in[16];
    const float* ln_w    = (const float*)d_in[17];
    const float* ln_b    = (const float*)d_in[18];
    const float* ff_w1   = (const float*)d_in[19];
    const float* ff_b1   = (const float*)d_in[20];
    const float* ff_w2   = (const float*)d_in[21];
    const float* ff_b2   = (const float*)d_in[22];
    const float* proj_w1 = (const float*)d_in[23];
    const float* proj_b1 = (const float*)d_in[24];
    const float* proj_w2 = (const float*)d_in[25];
    const float* proj_b2 = (const float*)d_in[26];
    const int*   basis   = (const int*)d_in[27];
    float* out = (float*)d_out;

    float *h_, *mem_, *qkv_, *att_, *ao_, *ff_, *p1_;
    cudaGetSymbolAddress((void**)&h_,   g_h);
    cudaGetSymbolAddress((void**)&mem_, g_mem);
    cudaGetSymbolAddress((void**)&qkv_, g_qkv);
    cudaGetSymbolAddress((void**)&att_, g_att);
    cudaGetSymbolAddress((void**)&ao_,  g_ao);
    cudaGetSymbolAddress((void**)&ff_,  g_ff);
    cudaGetSymbolAddress((void**)&p1_,  g_p1);

    const int M = NB * NS;         // 8192 tokens
    const float isq = 1.f / 16.f;  // 1/sqrt(256)

    // ---- input stage ----
    k_build_h1<<<(NB*NS*NHID)/256, 256>>>(target, bos, inp_w1, inp_b1, p1_);
    gemm_tn(p1_, NHID, inp_w2, NHID, h_, ND, inp_b2, nullptr, M, NHID, NHID, 1.f, 0);
    k_fill<<<(NB*NS*ND)/256, 256>>>(gs, prev, cur, h_, mem_);

    for (int l = 0; l < 3; l++) {
        const float* qkvw = sa_qkv_w + (long long)l * 3*ND*ND;
        const float* qkvb = sa_qkv_b + l * 3*ND;
        const float* ow   = sa_out_w + (long long)l * ND*ND;
        const float* ob   = sa_out_b + l * ND;

        // ===== self-attention (causal) =====
        gemm_tn(h_, ND, qkvw, ND, qkv_, 3*ND, qkvb, nullptr, M, 3*ND, ND, 1.f, 0);
        {
            dim3 g(NS/128, NS/128, NB*NNH);
            k_gemm<true><<<g, 256>>>(qkv_, 3*ND, (long long)NS*3*ND, NHD,
                                     qkv_ + ND, 3*ND, (long long)NS*3*ND, NHD,
                                     att_, NS, (long long)NNH*NS*NS, (long long)NS*NS,
                                     nullptr, nullptr, NS, NS, NHD, NNH, isq, 0, 1);
        }
        k_softmax<<<NB*NNH*NS, 256>>>(att_, 1);
        {
            dim3 g(NHD/128, NS/128, NB*NNH);
            k_gemm<false><<<g, 256>>>(att_, NS, (long long)NNH*NS*NS, (long long)NS*NS,
                                      qkv_ + 2*ND, 3*ND, (long long)NS*3*ND, NHD,
                                      ao_, ND, (long long)NS*ND, NHD,
                                      nullptr, nullptr, NS, NHD, NS, NNH, 1.f, 0, 0);
        }
        gemm_tn(ao_, ND, ow, ND, h_, ND, ob, h_, M, ND, ND, 1.f, 0);
        k_ln<<<M, 256>>>(h_, ln_w + (l*3 + 0)*ND, ln_b + (l*3 + 0)*ND);

        // ===== cross-attention =====
        qkvw = ca_qkv_w + (long long)l * 3*ND*ND;
        qkvb = ca_qkv_b + l * 3*ND;
        ow   = ca_out_w + (long long)l * ND*ND;
        ob   = ca_out_b + l * ND;
        gemm_tn(h_,   ND, qkvw,           ND, qkv_,      3*ND, qkvb,      nullptr, M,   ND, ND, 1.f, 0);
        gemm_tn(mem_, ND, qkvw + ND*ND,   ND, qkv_ + ND, 3*ND, qkvb + ND, nullptr, M, 2*ND, ND, 1.f, 0);
        {
            dim3 g(NS/128, NS/128, NB*NNH);
            k_gemm<true><<<g, 256>>>(qkv_, 3*ND, (long long)NS*3*ND, NHD,
                                     qkv_ + ND, 3*ND, (long long)NS*3*ND, NHD,
                                     att_, NS, (long long)NNH*NS*NS, (long long)NS*NS,
                                     nullptr, nullptr, NS, NS, NHD, NNH, isq, 0, 0);
        }
        k_softmax<<<NB*NNH*NS, 256>>>(att_, 0);
        {
            dim3 g(NHD/128, NS/128, NB*NNH);
            k_gemm<false><<<g, 256>>>(att_, NS, (long long)NNH*NS*NS, (long long)NS*NS,
                                      qkv_ + 2*ND, 3*ND, (long long)NS*3*ND, NHD,
                                      ao_, ND, (long long)NS*ND, NHD,
                                      nullptr, nullptr, NS, NHD, NS, NNH, 1.f, 0, 0);
        }
        gemm_tn(ao_, ND, ow, ND, h_, ND, ob, h_, M, ND, ND, 1.f, 0);
        k_ln<<<M, 256>>>(h_, ln_w + (l*3 + 1)*ND, ln_b + (l*3 + 1)*ND);

        // ===== feed-forward =====
        gemm_tn(h_, ND, ff_w1 + (long long)l*NDFF*ND, ND, ff_, NDFF,
                ff_b1 + l*NDFF, nullptr, M, NDFF, ND, 1.f, 1);
        gemm_tn(ff_, NDFF, ff_w2 + (long long)l*ND*NDFF, NDFF, h_, ND,
                ff_b2 + l*ND, h_, M, ND, NDFF, 1.f, 0);
        k_ln<<<M, 256>>>(h_, ln_w + (l*3 + 2)*ND, ln_b + (l*3 + 2)*ND);
    }

    // ---- output head ----
    gemm_tn(h_, ND, proj_w1, ND, p1_, NHID, proj_b1, nullptr, M, NHID, ND, 1.f, 2);
    k_final<<<(NB*NL*32 + 255)/256, 256>>>(p1_, proj_w2, proj_b2, basis, out);
}